// round 6
// baseline (speedup 1.0000x reference)
#include <cuda_runtime.h>
#include <cstdint>

#define N_ROWS 1000000
#define NTHREADS 256
#define WARPS 8
#define ROWS_PER_WARP 16
#define TILE_ROWS 128
#define NTILES ((N_ROWS + TILE_ROWS - 1) / TILE_ROWS)   // 7813
#define GRID 296                                        // 2 CTAs/SM x 148

// smem: W repacked [3][8ks][4q][32j] uint4 = 49152 B, A per warp 4096 B, bias 256 B
#define SMEM_W_BYTES  49152
#define SMEM_A_BYTES  (WARPS * 4096)
#define SMEM_BIAS_OFF (SMEM_W_BYTES + SMEM_A_BYTES)
#define SMEM_TOTAL    (SMEM_BIAS_OFF + 256)             // 82176 -> 2 CTAs/SM

__device__ __forceinline__ uint32_t tf32r(float f) {
    uint32_t u;
    asm("cvt.rna.tf32.f32 %0, %1;" : "=r"(u) : "f"(f));
    return u;
}

__device__ __forceinline__ void mma1688(float* d, const uint32_t* a, uint32_t b0, uint32_t b1) {
    asm volatile(
        "mma.sync.aligned.m16n8k8.row.col.f32.tf32.tf32.f32 "
        "{%0,%1,%2,%3}, {%4,%5,%6,%7}, {%8,%9}, {%0,%1,%2,%3};"
        : "+f"(d[0]), "+f"(d[1]), "+f"(d[2]), "+f"(d[3])
        : "r"(a[0]), "r"(a[1]), "r"(a[2]), "r"(a[3]), "r"(b0), "r"(b1));
}

// issue 8 LDG.128 covering half a 64-float row (c0 = 0 or 8, 16B chunks)
__device__ __forceinline__ void issue_ldg(float4 pref[8], const float* rowp, int c0) {
#pragma unroll
    for (int j = 0; j < 8; j++)
        pref[j] = __ldg(reinterpret_cast<const float4*>(rowp) + c0 + j);
}

// cvt.rna -> swizzled STS.128 into warp-private A tile (16 rows x 64 cols)
// swizzle: 16B-chunk c at row r lands at chunk (c ^ r)
__device__ __forceinline__ void sts_stage(uint32_t* sA, const float4 pref[8], int r, int c0) {
#pragma unroll
    for (int j = 0; j < 8; j++) {
        const int c = c0 + j;
        uint4 u;
        u.x = tf32r(pref[j].x); u.y = tf32r(pref[j].y);
        u.z = tf32r(pref[j].z); u.w = tf32r(pref[j].w);
        *reinterpret_cast<uint4*>(sA + r * 64 + ((c ^ r) << 2)) = u;
    }
}

// one t-stage of mma: 16 rows x 64 outs x 64 k, m16n8k8 frags
__device__ __forceinline__ void mma_stage(const uint32_t* sA, const uint4* sWt,
                                          float acc[8][4], int g, int q) {
#pragma unroll
    for (int ks = 0; ks < 8; ks++) {
        const int ch0 = 2 * ks, ch1 = 2 * ks + 1;
        uint32_t a[4];
        a[0] = sA[g * 64 + ((ch0 ^ g) << 2) + q];
        a[1] = sA[(g + 8) * 64 + ((ch0 ^ (g + 8)) << 2) + q];
        a[2] = sA[g * 64 + ((ch1 ^ g) << 2) + q];
        a[3] = sA[(g + 8) * 64 + ((ch1 ^ (g + 8)) << 2) + q];
        const uint4* bp = sWt + (ks * 4 + q) * 32;
#pragma unroll
        for (int nbl = 0; nbl < 4; nbl++) {
            const uint4 bv = bp[(nbl * 8 + g) ^ (q << 3)];
            mma1688(acc[nbl], a, bv.x, bv.y);
            mma1688(acc[nbl + 4], a, bv.z, bv.w);
        }
    }
}

__global__ void __launch_bounds__(NTHREADS, 2)
polyconv_kernel(const float* __restrict__ x,
                const int* __restrict__ li,
                const int* __restrict__ ri,
                const float* __restrict__ W,
                const float* __restrict__ bias,
                float* __restrict__ out) {
    extern __shared__ char smem[];
    uint4* sW4 = reinterpret_cast<uint4*>(smem);   // [3][8][4][32] uint4, 1024 per t
    const int tid = threadIdx.x;
    const int w = tid >> 5;
    const int l = tid & 31;
    uint32_t* sA = reinterpret_cast<uint32_t*>(smem + SMEM_W_BYTES + w * 4096);
    float* sbias = reinterpret_cast<float*>(smem + SMEM_BIAS_OFF);

    // ---- stage W: sW4[t][ks][q][j] = (W[k][n], W[k+4][n], W[k][n+32], W[k+4][n+32]),
    //      n = j ^ (q<<3), k = ks*8+q ; W gmem: W[n][t*64 + k]
    for (int i = tid; i < 3 * 8 * 4 * 32; i += NTHREADS) {
        const int j = i & 31;
        const int q = (i >> 5) & 3;
        const int ks = (i >> 7) & 7;
        const int t = i >> 10;
        const int n = j ^ (q << 3);
        const int k = ks * 8 + q;
        const float* wp = W + t * 64 + k;
        uint4 v;
        v.x = tf32r(wp[n * 192]);
        v.y = tf32r(wp[n * 192 + 4]);
        v.z = tf32r(wp[(n + 32) * 192]);
        v.w = tf32r(wp[(n + 32) * 192 + 4]);
        sW4[i] = v;
    }
    if (tid < 64) sbias[tid] = bias[tid];
    __syncthreads();

    // lane roles
    const int r = l >> 1;          // gather: row within warp tile (0..15)
    const int c0 = (l & 1) * 8;    // gather: which half-row (chunks)
    const int q = l & 3;           // mma: threadID_in_group
    const int g = l >> 2;          // mma: groupID
    const int myrow = w * ROWS_PER_WARP + r;

    float acc[8][4];
#pragma unroll
    for (int nb = 0; nb < 8; nb++)
#pragma unroll
        for (int j = 0; j < 4; j++) acc[nb][j] = 0.0f;

    float4 pref[8];
    int tile = blockIdx.x;

    int gcur = tile * TILE_ROWS + myrow;
    if (gcur >= N_ROWS) gcur = N_ROWS - 1;
    int ilc = __ldg(li + gcur);
    int irc = __ldg(ri + gcur);
    issue_ldg(pref, x + (size_t)gcur * 64, c0);

    while (true) {
        const int ntile = tile + GRID;
        const bool nv = (ntile < NTILES);
        int gn = nv ? ntile * TILE_ROWS + myrow : gcur;
        if (gn >= N_ROWS) gn = N_ROWS - 1;
        const int iln = __ldg(li + gn);   // prefetched a full tile ahead
        const int irn = __ldg(ri + gn);

        // ---- t = 0 ----
        sts_stage(sA, pref, r, c0);
        issue_ldg(pref, x + (size_t)ilc * 64, c0);
        __syncwarp();
        mma_stage(sA, sW4, acc, g, q);
        __syncwarp();
        // ---- t = 1 ----
        sts_stage(sA, pref, r, c0);
        issue_ldg(pref, x + (size_t)irc * 64, c0);
        __syncwarp();
        mma_stage(sA, sW4 + 1024, acc, g, q);
        __syncwarp();
        // ---- t = 2 ----
        sts_stage(sA, pref, r, c0);
        if (nv) issue_ldg(pref, x + (size_t)gn * 64, c0);
        __syncwarp();
        mma_stage(sA, sW4 + 2048, acc, g, q);

        // ---- epilogue: bias + store, reset acc ----
        const int row0 = tile * TILE_ROWS + w * ROWS_PER_WARP + g;
#pragma unroll
        for (int nb = 0; nb < 8; nb++) {
            const int col = nb * 8 + q * 2;
            const float2 bb = *reinterpret_cast<const float2*>(sbias + col);
            if (row0 < N_ROWS) {
                float2 v;
                v.x = acc[nb][0] + bb.x;
                v.y = acc[nb][1] + bb.y;
                *reinterpret_cast<float2*>(out + (size_t)row0 * 64 + col) = v;
            }
            if (row0 + 8 < N_ROWS) {
                float2 v;
                v.x = acc[nb][2] + bb.x;
                v.y = acc[nb][3] + bb.y;
                *reinterpret_cast<float2*>(out + (size_t)(row0 + 8) * 64 + col) = v;
            }
            acc[nb][0] = acc[nb][1] = acc[nb][2] = acc[nb][3] = 0.0f;
        }
        __syncwarp();

        if (!nv) break;
        tile = ntile;
        gcur = gn;
        ilc = iln;
        irc = irn;
    }
}

extern "C" void kernel_launch(void* const* d_in, const int* in_sizes, int n_in,
                              void* d_out, int out_size) {
    const float* x  = (const float*)d_in[0];
    const int*   li = (const int*)d_in[1];
    const int*   ri = (const int*)d_in[2];
    const float* W  = (const float*)d_in[3];
    const float* b  = (const float*)d_in[4];
    float* out = (float*)d_out;

    cudaFuncSetAttribute(polyconv_kernel,
                         cudaFuncAttributeMaxDynamicSharedMemorySize, SMEM_TOTAL);
    polyconv_kernel<<<GRID, NTHREADS, SMEM_TOTAL>>>(x, li, ri, W, b, out);
}

// round 7
// speedup vs baseline: 1.9150x; 1.9150x over previous
#include <cuda_runtime.h>
#include <cstdint>

#define N_ROWS 1000000
#define NTHREADS 256
#define WARPS 8
#define ROWS_PER_WARP 32
#define TILE_ROWS 256
#define NTILES ((N_ROWS + TILE_ROWS - 1) / TILE_ROWS)   // 3907
#define GRID 152

// smem: W repacked [3][8ks][4q][32j] uint4 = 49152 B
//       A: per warp 2 buffers x (32 rows x 64 fp32) = 2 x 8192 B
//       bias 256 B
#define SMEM_W_BYTES  49152
#define SMEM_A_OFF    SMEM_W_BYTES
#define SMEM_A_BYTES  (WARPS * 2 * 8192)
#define SMEM_BIAS_OFF (SMEM_A_OFF + SMEM_A_BYTES)
#define SMEM_TOTAL    (SMEM_BIAS_OFF + 256)             // 180480 -> 1 CTA/SM

__device__ __forceinline__ uint32_t tf32r(float f) {
    uint32_t u;
    asm("cvt.rna.tf32.f32 %0, %1;" : "=r"(u) : "f"(f));
    return u;
}

__device__ __forceinline__ uint32_t smem_u32(const void* p) {
    uint32_t a;
    asm("{ .reg .u64 t; cvta.to.shared.u64 t, %1; cvt.u32.u64 %0, t; }"
        : "=r"(a) : "l"(p));
    return a;
}

__device__ __forceinline__ void mma1688(float* d, const uint32_t* a, uint32_t b0, uint32_t b1) {
    asm volatile(
        "mma.sync.aligned.m16n8k8.row.col.f32.tf32.tf32.f32 "
        "{%0,%1,%2,%3}, {%4,%5,%6,%7}, {%8,%9}, {%0,%1,%2,%3};"
        : "+f"(d[0]), "+f"(d[1]), "+f"(d[2]), "+f"(d[3])
        : "r"(a[0]), "r"(a[1]), "r"(a[2]), "r"(a[3]), "r"(b0), "r"(b1));
}

__device__ __forceinline__ void cpasync16(uint32_t dst, const void* src) {
    asm volatile("cp.async.cg.shared.global [%0], [%1], 16;" :: "r"(dst), "l"(src));
}
__device__ __forceinline__ void cp_commit() {
    asm volatile("cp.async.commit_group;" ::: "memory");
}
__device__ __forceinline__ void cp_wait1() {
    asm volatile("cp.async.wait_group 1;" ::: "memory");
}

// lane l stages row l of the 32-row tile: 16 x cp.async(16B), chunk-swizzled j -> j^(l&15)
__device__ __forceinline__ void issue_stage(uint32_t bufb, const float* __restrict__ xrow, int l) {
    const uint32_t rowb = bufb + (uint32_t)l * 256u;
    const char* s = reinterpret_cast<const char*>(xrow);
#pragma unroll
    for (int j = 0; j < 16; j++)
        cpasync16(rowb + ((uint32_t)(j ^ (l & 15)) << 4), s + j * 16);
}

// one t-stage: 32 rows x 64 cols x 64 k. A fp32 in smem (swizzled), cvt.rna here.
__device__ __forceinline__ void mma_stage(const float* __restrict__ sA,
                                          const uint4* __restrict__ sWt,
                                          float acc[2][8][4], int g, int q) {
#pragma unroll
    for (int ks = 0; ks < 8; ks++) {
        uint32_t a[2][4];
#pragma unroll
        for (int m = 0; m < 2; m++) {
            const int r0 = m * 16 + g;       // r0 & 15 == g
            const int r1 = r0 + 8;           // r1 & 15 == g + 8
            a[m][0] = tf32r(sA[r0 * 64 + (((2 * ks) ^ g) << 2) + q]);
            a[m][1] = tf32r(sA[r1 * 64 + (((2 * ks) ^ (g + 8)) << 2) + q]);
            a[m][2] = tf32r(sA[r0 * 64 + (((2 * ks + 1) ^ g) << 2) + q]);
            a[m][3] = tf32r(sA[r1 * 64 + (((2 * ks + 1) ^ (g + 8)) << 2) + q]);
        }
        const uint4* bp = sWt + (ks * 4 + q) * 32;
#pragma unroll
        for (int nbl = 0; nbl < 4; nbl++) {
            const uint4 bv = bp[(nbl * 8 + g) ^ (q << 3)];
            mma1688(acc[0][nbl], a[0], bv.x, bv.y);
            mma1688(acc[0][nbl + 4], a[0], bv.z, bv.w);
            mma1688(acc[1][nbl], a[1], bv.x, bv.y);
            mma1688(acc[1][nbl + 4], a[1], bv.z, bv.w);
        }
    }
}

__global__ void __launch_bounds__(NTHREADS, 1)
polyconv_kernel(const float* __restrict__ x,
                const int* __restrict__ li,
                const int* __restrict__ ri,
                const float* __restrict__ W,
                const float* __restrict__ bias,
                float* __restrict__ out) {
    extern __shared__ char smem[];
    uint4* sW4 = reinterpret_cast<uint4*>(smem);   // [3][8][4][32] uint4
    const int tid = threadIdx.x;
    const int w = tid >> 5;
    const int l = tid & 31;
    float* sA = reinterpret_cast<float*>(smem + SMEM_A_OFF + w * 16384);  // 2 bufs x 2048 fp32
    float* sbias = reinterpret_cast<float*>(smem + SMEM_BIAS_OFF);
    const uint32_t sAu = smem_u32(sA);

    // ---- stage W (verified packing): sW4[t][ks][q][j] =
    //      (W[k][n], W[k+4][n], W[k][n+32], W[k+4][n+32]); n = j^(q<<3), k = ks*8+q
    for (int i = tid; i < 3 * 8 * 4 * 32; i += NTHREADS) {
        const int j = i & 31;
        const int q = (i >> 5) & 3;
        const int ks = (i >> 7) & 7;
        const int t = i >> 10;
        const int n = j ^ (q << 3);
        const int k = ks * 8 + q;
        const float* wp = W + t * 64 + k;
        uint4 v;
        v.x = tf32r(wp[n * 192]);
        v.y = tf32r(wp[n * 192 + 4]);
        v.z = tf32r(wp[(n + 32) * 192]);
        v.w = tf32r(wp[(n + 32) * 192 + 4]);
        sW4[i] = v;
    }
    if (tid < 64) sbias[tid] = bias[tid];
    __syncthreads();

    const int q = l & 3;
    const int g = l >> 2;

    float acc[2][8][4];
#pragma unroll
    for (int m = 0; m < 2; m++)
#pragma unroll
        for (int nb = 0; nb < 8; nb++)
#pragma unroll
            for (int jj = 0; jj < 4; jj++) acc[m][nb][jj] = 0.0f;

    // ---- prologue: tile0 indices + issue t0 into buf0 ----
    int tile = blockIdx.x;
    int gcur = tile * TILE_ROWS + w * ROWS_PER_WARP + l;
    if (gcur >= N_ROWS) gcur = N_ROWS - 1;
    int ilc = __ldg(li + gcur);
    int irc = __ldg(ri + gcur);
    issue_stage(sAu, x + (size_t)gcur * 64, l);
    cp_commit();
    uint32_t cur = 0;   // buffer holding the in-flight/current t0

    while (true) {
        const int ntile = tile + GRID;
        const bool nv = (ntile < NTILES);
        int gn = nv ? ntile * TILE_ROWS + w * ROWS_PER_WARP + l : gcur;
        if (gn >= N_ROWS) gn = N_ROWS - 1;
        const int iln = __ldg(li + gn);
        const int irn = __ldg(ri + gn);

        const float* bufc = sA + (cur ? 2048 : 0);
        const float* bufo = sA + (cur ? 0 : 2048);
        const uint32_t bufcu = sAu + (cur ? 8192u : 0u);
        const uint32_t bufou = sAu + (cur ? 0u : 8192u);

        // ---- t0 (x) ----
        issue_stage(bufou, x + (size_t)ilc * 64, l);   // t1 -> other buf
        cp_commit();
        cp_wait1();
        __syncwarp();
        mma_stage(bufc, sW4, acc, g, q);
        __syncwarp();
        // ---- t1 (x[L]) ----
        issue_stage(bufcu, x + (size_t)irc * 64, l);   // t2 -> cur buf
        cp_commit();
        cp_wait1();
        __syncwarp();
        mma_stage(bufo, sW4 + 1024, acc, g, q);
        __syncwarp();
        // ---- t2 (x[R]) ----
        issue_stage(bufou, x + (size_t)gn * 64, l);    // next t0 -> other buf
        cp_commit();
        cp_wait1();
        __syncwarp();
        mma_stage(bufc, sW4 + 2048, acc, g, q);

        // ---- epilogue: bias + store, reset acc ----
        const int rowb = tile * TILE_ROWS + w * ROWS_PER_WARP + g;
#pragma unroll
        for (int nb = 0; nb < 8; nb++) {
            const int col = nb * 8 + q * 2;
            const float2 bb = *reinterpret_cast<const float2*>(sbias + col);
#pragma unroll
            for (int m = 0; m < 2; m++) {
                const int r0 = rowb + m * 16;
                if (r0 < N_ROWS) {
                    float2 v;
                    v.x = acc[m][nb][0] + bb.x;
                    v.y = acc[m][nb][1] + bb.y;
                    *reinterpret_cast<float2*>(out + (size_t)r0 * 64 + col) = v;
                }
                if (r0 + 8 < N_ROWS) {
                    float2 v;
                    v.x = acc[m][nb][2] + bb.x;
                    v.y = acc[m][nb][3] + bb.y;
                    *reinterpret_cast<float2*>(out + (size_t)(r0 + 8) * 64 + col) = v;
                }
                acc[m][nb][0] = acc[m][nb][1] = acc[m][nb][2] = acc[m][nb][3] = 0.0f;
            }
        }
        __syncwarp();

        if (!nv) break;
        tile = ntile;
        gcur = gn;
        ilc = iln;
        irc = irn;
        cur ^= 1;
    }
}

extern "C" void kernel_launch(void* const* d_in, const int* in_sizes, int n_in,
                              void* d_out, int out_size) {
    const float* x  = (const float*)d_in[0];
    const int*   li = (const int*)d_in[1];
    const int*   ri = (const int*)d_in[2];
    const float* W  = (const float*)d_in[3];
    const float* b  = (const float*)d_in[4];
    float* out = (float*)d_out;

    cudaFuncSetAttribute(polyconv_kernel,
                         cudaFuncAttributeMaxDynamicSharedMemorySize, SMEM_TOTAL);
    polyconv_kernel<<<GRID, NTHREADS, SMEM_TOTAL>>>(x, li, ri, W, b, out);
}

// round 8
// speedup vs baseline: 4.1616x; 2.1731x over previous
#include <cuda_runtime.h>
#include <cstdint>

#define N_ROWS 1000000
#define NTHREADS 256
#define WARPS 8
#define ROWS_PER_WARP 32
#define TILE_ROWS 256
#define NTILES ((N_ROWS + TILE_ROWS - 1) / TILE_ROWS)   // 3907
#define GRID 152

// smem: W repacked [3][8ks][4q][32j] uint4 = 49152 B
//       A: per warp 2 buffers x (32 rows x 64 fp32) = 2 x 8192 B
//       bias 256 B
#define SMEM_W_BYTES  49152
#define SMEM_A_OFF    SMEM_W_BYTES
#define SMEM_A_BYTES  (WARPS * 2 * 8192)
#define SMEM_BIAS_OFF (SMEM_A_OFF + SMEM_A_BYTES)
#define SMEM_TOTAL    (SMEM_BIAS_OFF + 256)             // 180480 -> 1 CTA/SM

__device__ __forceinline__ uint32_t tf32r(float f) {
    uint32_t u;
    asm("cvt.rna.tf32.f32 %0, %1;" : "=r"(u) : "f"(f));
    return u;
}

__device__ __forceinline__ uint32_t smem_u32(const void* p) {
    uint32_t a;
    asm("{ .reg .u64 t; cvta.to.shared.u64 t, %1; cvt.u32.u64 %0, t; }"
        : "=r"(a) : "l"(p));
    return a;
}

__device__ __forceinline__ void mma1688(float* d, const uint32_t* a, uint32_t b0, uint32_t b1) {
    asm volatile(
        "mma.sync.aligned.m16n8k8.row.col.f32.tf32.tf32.f32 "
        "{%0,%1,%2,%3}, {%4,%5,%6,%7}, {%8,%9}, {%0,%1,%2,%3};"
        : "+f"(d[0]), "+f"(d[1]), "+f"(d[2]), "+f"(d[3])
        : "r"(a[0]), "r"(a[1]), "r"(a[2]), "r"(a[3]), "r"(b0), "r"(b1));
}

__device__ __forceinline__ void cpasync16(uint32_t dst, const void* src) {
    asm volatile("cp.async.cg.shared.global [%0], [%1], 16;" :: "r"(dst), "l"(src));
}
__device__ __forceinline__ void cp_commit() {
    asm volatile("cp.async.commit_group;" ::: "memory");
}
__device__ __forceinline__ void cp_wait1() {
    asm volatile("cp.async.wait_group 1;" ::: "memory");
}

// Gather 32 rows; 16 lanes cover one row's 16 chunks -> 2 rows per cp.async instr
// (4 cache lines each). Row indices broadcast from per-lane register via shfl.
// dst chunk swizzle: c -> c ^ (row & 15).
__device__ __forceinline__ void issue_stage_idx(uint32_t bufb, const float* __restrict__ x,
                                                int idxreg, int l) {
    const int sub = l >> 4;
    const int c = l & 15;
#pragma unroll
    for (int i = 0; i < 16; i++) {
        const int rl = 2 * i + sub;  // row within 32-row tile
        const int src = __shfl_sync(0xffffffffu, idxreg, rl);
        const uint32_t dst = bufb + (uint32_t)rl * 256u + ((uint32_t)(c ^ (rl & 15)) << 4);
        cpasync16(dst, reinterpret_cast<const char*>(x + (size_t)src * 64) + c * 16);
    }
}

// Identity gather: rows base2 + rl (clamped).
__device__ __forceinline__ void issue_stage_id(uint32_t bufb, const float* __restrict__ x,
                                               int base2, int l) {
    const int sub = l >> 4;
    const int c = l & 15;
#pragma unroll
    for (int i = 0; i < 16; i++) {
        const int rl = 2 * i + sub;
        int src = base2 + rl;
        if (src >= N_ROWS) src = N_ROWS - 1;
        const uint32_t dst = bufb + (uint32_t)rl * 256u + ((uint32_t)(c ^ (rl & 15)) << 4);
        cpasync16(dst, reinterpret_cast<const char*>(x + (size_t)src * 64) + c * 16);
    }
}

// one t-stage: 32 rows x 64 cols x 64 k. A fp32 in smem (swizzled), cvt.rna here.
// B LDS swizzle ^(q<<1): conflict-free phases.
__device__ __forceinline__ void mma_stage(const float* __restrict__ sA,
                                          const uint4* __restrict__ sWt,
                                          float acc[2][8][4], int g, int q) {
#pragma unroll
    for (int ks = 0; ks < 8; ks++) {
        uint32_t a[2][4];
#pragma unroll
        for (int m = 0; m < 2; m++) {
            const int r0 = m * 16 + g;       // r0 & 15 == g
            const int r1 = r0 + 8;           // r1 & 15 == g + 8
            a[m][0] = tf32r(sA[r0 * 64 + (((2 * ks) ^ g) << 2) + q]);
            a[m][1] = tf32r(sA[r1 * 64 + (((2 * ks) ^ (g + 8)) << 2) + q]);
            a[m][2] = tf32r(sA[r0 * 64 + (((2 * ks + 1) ^ g) << 2) + q]);
            a[m][3] = tf32r(sA[r1 * 64 + (((2 * ks + 1) ^ (g + 8)) << 2) + q]);
        }
        const uint4* bp = sWt + (ks * 4 + q) * 32;
#pragma unroll
        for (int nbl = 0; nbl < 4; nbl++) {
            const uint4 bv = bp[(nbl * 8 + g) ^ (q << 1)];
            mma1688(acc[0][nbl], a[0], bv.x, bv.y);
            mma1688(acc[0][nbl + 4], a[0], bv.z, bv.w);
            mma1688(acc[1][nbl], a[1], bv.x, bv.y);
            mma1688(acc[1][nbl + 4], a[1], bv.z, bv.w);
        }
    }
}

__global__ void __launch_bounds__(NTHREADS, 1)
polyconv_kernel(const float* __restrict__ x,
                const int* __restrict__ li,
                const int* __restrict__ ri,
                const float* __restrict__ W,
                const float* __restrict__ bias,
                float* __restrict__ out) {
    extern __shared__ char smem[];
    uint4* sW4 = reinterpret_cast<uint4*>(smem);   // [3][8][4][32] uint4
    const int tid = threadIdx.x;
    const int w = tid >> 5;
    const int l = tid & 31;
    float* sA = reinterpret_cast<float*>(smem + SMEM_A_OFF + w * 16384);  // 2 bufs x 2048 fp32
    float* sbias = reinterpret_cast<float*>(smem + SMEM_BIAS_OFF);
    const uint32_t sAu = smem_u32(sA);

    // ---- stage W: sW4[t][ks][q][j] = (W[k][n], W[k+4][n], W[k][n+32], W[k+4][n+32]),
    //      n = j ^ (q<<1), k = ks*8+q ; W gmem: W[n][t*64 + k]
    for (int i = tid; i < 3 * 8 * 4 * 32; i += NTHREADS) {
        const int j = i & 31;
        const int q = (i >> 5) & 3;
        const int ks = (i >> 7) & 7;
        const int t = i >> 10;
        const int n = j ^ (q << 1);
        const int k = ks * 8 + q;
        const float* wp = W + t * 64 + k;
        uint4 v;
        v.x = tf32r(wp[n * 192]);
        v.y = tf32r(wp[n * 192 + 4]);
        v.z = tf32r(wp[(n + 32) * 192]);
        v.w = tf32r(wp[(n + 32) * 192 + 4]);
        sW4[i] = v;
    }
    if (tid < 64) sbias[tid] = bias[tid];
    __syncthreads();

    const int q = l & 3;
    const int g = l >> 2;

    float acc[2][8][4];
#pragma unroll
    for (int m = 0; m < 2; m++)
#pragma unroll
        for (int nb = 0; nb < 8; nb++)
#pragma unroll
            for (int jj = 0; jj < 4; jj++) acc[m][nb][jj] = 0.0f;

    // ---- prologue ----
    int tile = blockIdx.x;
    int base2 = tile * TILE_ROWS + w * ROWS_PER_WARP;
    int idxrow = base2 + l;
    if (idxrow >= N_ROWS) idxrow = N_ROWS - 1;
    int ilc = __ldg(li + idxrow);   // per-lane: index for row l of this warp tile
    int irc = __ldg(ri + idxrow);
    issue_stage_id(sAu, x, base2, l);
    cp_commit();
    uint32_t cur = 0;

    while (true) {
        const int ntile = tile + GRID;
        const bool nv = (ntile < NTILES);
        const int nbase2 = (nv ? ntile : tile) * TILE_ROWS + w * ROWS_PER_WARP;
        int nidxrow = nbase2 + l;
        if (nidxrow >= N_ROWS) nidxrow = N_ROWS - 1;
        const int iln = __ldg(li + nidxrow);
        const int irn = __ldg(ri + nidxrow);

        const float* bufc = sA + (cur ? 2048 : 0);
        const float* bufo = sA + (cur ? 0 : 2048);
        const uint32_t bufcu = sAu + (cur ? 8192u : 0u);
        const uint32_t bufou = sAu + (cur ? 0u : 8192u);

        // ---- t0 (x) ----
        issue_stage_idx(bufou, x, ilc, l);   // t1 -> other buf
        cp_commit();
        cp_wait1();
        __syncwarp();
        mma_stage(bufc, sW4, acc, g, q);
        __syncwarp();
        // ---- t1 (x[L]) ----
        issue_stage_idx(bufcu, x, irc, l);   // t2 -> cur buf
        cp_commit();
        cp_wait1();
        __syncwarp();
        mma_stage(bufo, sW4 + 1024, acc, g, q);
        __syncwarp();
        // ---- t2 (x[R]) ----
        issue_stage_id(bufou, x, nbase2, l); // next t0 -> other buf
        cp_commit();
        cp_wait1();
        __syncwarp();
        mma_stage(bufc, sW4 + 2048, acc, g, q);

        // ---- epilogue: bias + store, reset acc ----
        const int rowb = base2 + g;
#pragma unroll
        for (int nb = 0; nb < 8; nb++) {
            const int col = nb * 8 + q * 2;
            const float2 bb = *reinterpret_cast<const float2*>(sbias + col);
#pragma unroll
            for (int m = 0; m < 2; m++) {
                const int r0 = rowb + m * 16;
                if (r0 < N_ROWS) {
                    float2 v;
                    v.x = acc[m][nb][0] + bb.x;
                    v.y = acc[m][nb][1] + bb.y;
                    *reinterpret_cast<float2*>(out + (size_t)r0 * 64 + col) = v;
                }
                if (r0 + 8 < N_ROWS) {
                    float2 v;
                    v.x = acc[m][nb][2] + bb.x;
                    v.y = acc[m][nb][3] + bb.y;
                    *reinterpret_cast<float2*>(out + (size_t)(r0 + 8) * 64 + col) = v;
                }
                acc[m][nb][0] = acc[m][nb][1] = acc[m][nb][2] = acc[m][nb][3] = 0.0f;
            }
        }
        __syncwarp();

        if (!nv) break;
        tile = ntile;
        base2 = nbase2;
        ilc = iln;
        irc = irn;
        cur ^= 1;
    }
}

extern "C" void kernel_launch(void* const* d_in, const int* in_sizes, int n_in,
                              void* d_out, int out_size) {
    const float* x  = (const float*)d_in[0];
    const int*   li = (const int*)d_in[1];
    const int*   ri = (const int*)d_in[2];
    const float* W  = (const float*)d_in[3];
    const float* b  = (const float*)d_in[4];
    float* out = (float*)d_out;

    cudaFuncSetAttribute(polyconv_kernel,
                         cudaFuncAttributeMaxDynamicSharedMemorySize, SMEM_TOTAL);
    polyconv_kernel<<<GRID, NTHREADS, SMEM_TOTAL>>>(x, li, ri, W, b, out);
}